// round 9
// baseline (speedup 1.0000x reference)
#include <cuda_runtime.h>
#include <math.h>

#define BB 8
#define SS 4096
#define HH 4096
#define DD 128
#define NMAX 64
#define NT 64
#define HT 64            /* HH / NT */
#define TPB 256

// -------- persistent scratch: zero at load; attn tail re-zeros each replay --
__device__ float g_K[BB][NMAX][DD];   // 256 KB
__device__ float g_Q[BB][DD];
__device__ float g_V[BB][NMAX];
__device__ float g_rew[BB];
__device__ int   g_arrive[BB];        // per-batch arrival counters
__device__ int   g_done;              // cross-batch arrival counter

__device__ __forceinline__ void red_f32(float* p, float v) {
    asm volatile("red.global.add.f32 [%0], %1;" :: "l"(p), "f"(v) : "memory");
}

// ---------------------------------------------------------------------------
// ONE fused kernel. grid=(NT, BB), 256 threads.
// Each thread owns output dim d = tid&127 and h-half = tid>>7 (32 h values,
// 16 f32x2 Wk registers). Partials RED into g_K/g_Q/g_V; the halves merge
// for free through the atomics.
// Phase 2 (last block per batch): attention + reward + accumulator re-zero.
// Phase 3 (last batch): pairwise loss + output.
// ---------------------------------------------------------------------------
__global__ void __launch_bounds__(TPB)
k_fused(const float* __restrict__ hid,
        const int*   __restrict__ mask,
        const float* __restrict__ Wq,
        const float* __restrict__ bq,
        const float* __restrict__ Wk,
        const float* __restrict__ bk,
        const float* __restrict__ Wr,
        const float* __restrict__ br,
        float* __restrict__ out, int out_size) {
    const int b    = blockIdx.y;
    const int tile = blockIdx.x;
    const int h0   = tile * HT;
    const int tid  = threadIdx.x;
    const int lane = tid & 31, warp = tid >> 5;    // 8 warps
    const int d    = tid & (DD - 1);
    const int half = tid >> 7;                      // 0/1
    const int hb   = h0 + half * (HT / 2);          // this thread's h base

    __shared__ __align__(16) float buf[NMAX * DD];  // 32KB: proj 16KB, attn all
    __shared__ float swr[HT];
    __shared__ float qs[DD];
    __shared__ float lg[NMAX];
    __shared__ float sv[NMAX];
    __shared__ int   s_pos[NMAX];
    __shared__ int   s_wsum[8];
    __shared__ int   s_cnt;
    __shared__ int   s_last;

    // ---- issue Wk register preload FIRST (overlaps the scan below) ----
    unsigned long long wk2[HT / 4];                 // 16 pairs = 32 regs
#pragma unroll
    for (int j = 0; j < HT / 4; j++) {
        float w0 = Wk[(size_t)(hb + 2 * j) * DD + d];
        float w1 = Wk[(size_t)(hb + 2 * j + 1) * DD + d];
        asm("mov.b64 %0,{%1,%2};" : "=l"(wk2[j]) : "f"(w0), "f"(w1));
    }
    if (tid < HT) swr[tid] = Wr[h0 + tid];

    // ---- inline mask scan: single pass, 256 threads x 16 elements ----
    {
        const int base = tid * 16;
        const int4* m4 = (const int4*)(mask + b * SS + base);
        int v[16];
        { int4 t0 = m4[0], t1 = m4[1], t2 = m4[2], t3 = m4[3];
          v[0]=t0.x; v[1]=t0.y; v[2]=t0.z; v[3]=t0.w;
          v[4]=t1.x; v[5]=t1.y; v[6]=t1.z; v[7]=t1.w;
          v[8]=t2.x; v[9]=t2.y; v[10]=t2.z; v[11]=t2.w;
          v[12]=t3.x; v[13]=t3.y; v[14]=t3.z; v[15]=t3.w; }
        int c = 0;
#pragma unroll
        for (int j = 0; j < 16; j++) c += (v[j] > 0);
        int x = c;
#pragma unroll
        for (int off = 1; off < 32; off <<= 1) {
            int y = __shfl_up_sync(0xffffffffu, x, off);
            if (lane >= off) x += y;
        }
        if (lane == 31) s_wsum[warp] = x;
        __syncthreads();
        int pre = 0;
#pragma unroll
        for (int w = 0; w < 8; w++) pre += (w < warp) ? s_wsum[w] : 0;
        int r = pre + x - c;
#pragma unroll
        for (int j = 0; j < 16; j++) {
            if (v[j] > 0) { if (r < NMAX) s_pos[r] = base + j; r++; }
        }
        if (tid == 0) {
            int tot = 0;
#pragma unroll
            for (int w = 0; w < 8; w++) tot += s_wsum[w];
            s_cnt = (tot < NMAX) ? tot : NMAX;
        }
        __syncthreads();
    }
    const int cnt  = s_cnt;
    const int last = cnt - 1;

    // ---- preload ALL sentence-row slices into smem (one MLP burst) ----
    {
        int tot4 = cnt * (HT / 4);
        float4* b4 = (float4*)buf;
        for (int i = tid; i < tot4; i += TPB) {
            int row = i >> 4;            // HT/4 = 16
            int c4  = i & 15;
            b4[i] = *(const float4*)(hid +
                ((size_t)b * SS + s_pos[row]) * HH + h0 + c4 * 4);
        }
    }
    __syncthreads();

    // ---- mainloop: 2 rows/iter, 4 FFMA2 chains, direct RED flush ----
    int i = 0;
    for (; i + 2 <= cnt; i += 2) {
        const ulonglong2* r0 = (const ulonglong2*)&buf[i * HT + half * (HT / 2)];
        const ulonglong2* r1 = (const ulonglong2*)&buf[(i + 1) * HT + half * (HT / 2)];
        unsigned long long a00 = 0ull, a01 = 0ull, a10 = 0ull, a11 = 0ull;
#pragma unroll
        for (int j = 0; j < HT / 8; j++) {           // 8 iterations
            ulonglong2 x0 = r0[j], x1 = r1[j];
            asm("fma.rn.f32x2 %0,%1,%2,%0;" : "+l"(a00) : "l"(x0.x), "l"(wk2[2*j]));
            asm("fma.rn.f32x2 %0,%1,%2,%0;" : "+l"(a10) : "l"(x1.x), "l"(wk2[2*j]));
            asm("fma.rn.f32x2 %0,%1,%2,%0;" : "+l"(a01) : "l"(x0.y), "l"(wk2[2*j+1]));
            asm("fma.rn.f32x2 %0,%1,%2,%0;" : "+l"(a11) : "l"(x1.y), "l"(wk2[2*j+1]));
        }
        float l0,h0f,l1,h1f,l2,h2f,l3,h3f;
        asm("mov.b64 {%0,%1},%2;" : "=f"(l0), "=f"(h0f) : "l"(a00));
        asm("mov.b64 {%0,%1},%2;" : "=f"(l1), "=f"(h1f) : "l"(a01));
        asm("mov.b64 {%0,%1},%2;" : "=f"(l2), "=f"(h2f) : "l"(a10));
        asm("mov.b64 {%0,%1},%2;" : "=f"(l3), "=f"(h3f) : "l"(a11));
        red_f32(&g_K[b][i][d],     (l0 + h0f) + (l1 + h1f));
        red_f32(&g_K[b][i + 1][d], (l2 + h2f) + (l3 + h3f));

        if (tid < HT) {   // V partials for both rows (warps 0,1)
            float vp0 = buf[i * HT + tid] * swr[tid];
            float vp1 = buf[(i + 1) * HT + tid] * swr[tid];
#pragma unroll
            for (int off = 16; off; off >>= 1) {
                vp0 += __shfl_down_sync(0xffffffffu, vp0, off);
                vp1 += __shfl_down_sync(0xffffffffu, vp1, off);
            }
            if (lane == 0) {
                red_f32(&g_V[b][i], vp0);
                red_f32(&g_V[b][i + 1], vp1);
            }
        }
    }
    if (i < cnt) {       // odd tail row
        const ulonglong2* r0 = (const ulonglong2*)&buf[i * HT + half * (HT / 2)];
        unsigned long long a00 = 0ull, a01 = 0ull;
#pragma unroll
        for (int j = 0; j < HT / 8; j++) {
            ulonglong2 x0 = r0[j];
            asm("fma.rn.f32x2 %0,%1,%2,%0;" : "+l"(a00) : "l"(x0.x), "l"(wk2[2*j]));
            asm("fma.rn.f32x2 %0,%1,%2,%0;" : "+l"(a01) : "l"(x0.y), "l"(wk2[2*j+1]));
        }
        float l0,h0f,l1,h1f;
        asm("mov.b64 {%0,%1},%2;" : "=f"(l0), "=f"(h0f) : "l"(a00));
        asm("mov.b64 {%0,%1},%2;" : "=f"(l1), "=f"(h1f) : "l"(a01));
        red_f32(&g_K[b][i][d], (l0 + h0f) + (l1 + h1f));
        if (tid < HT) {
            float vp0 = buf[i * HT + tid] * swr[tid];
#pragma unroll
            for (int off = 16; off; off >>= 1)
                vp0 += __shfl_down_sync(0xffffffffu, vp0, off);
            if (lane == 0) red_f32(&g_V[b][i], vp0);
        }
    }

    // ---- Q: this thread's 32-h slice of the last sentence row ----
    {
        const float* srow = &buf[last * HT + half * (HT / 2)];
        float aq0 = 0.0f, aq1 = 0.0f;
#pragma unroll
        for (int j = 0; j < HT / 2; j += 2) {
            aq0 += srow[j]     * Wq[(size_t)(hb + j) * DD + d];
            aq1 += srow[j + 1] * Wq[(size_t)(hb + j + 1) * DD + d];
        }
        red_f32(&g_Q[b][d], aq0 + aq1);
    }

    // ---- arrival: last block of this batch proceeds to attention ----
    __threadfence();
    __syncthreads();
    if (tid == 0) {
        int old = atomicAdd(&g_arrive[b], 1);
        s_last = (old == NT - 1);
        if (s_last) g_arrive[b] = 0;     // reset for next replay
    }
    __syncthreads();
    if (!s_last) return;
    __threadfence();                     // acquire: make all REDs visible

    // =================== attention tail (1 block per batch) ================
    // burst g_K[b] into smem; zero it behind the read
    {
        float4* b4 = (float4*)buf;
        float4 z = make_float4(0.f, 0.f, 0.f, 0.f);
        int tot = cnt * (DD / 4);
        for (int ii = tid; ii < tot; ii += TPB) {
            int row = ii >> 5, c4 = ii & 31;
            float4 v = *(const float4*)&g_K[b][row][c4 * 4];
            b4[ii] = v;
            *(float4*)&g_K[b][row][c4 * 4] = z;
        }
    }
    if (tid < NMAX) { sv[tid] = g_V[b][tid]; g_V[b][tid] = 0.0f; }

    const float LN_THETA = 9.210340371976184f;   // ln(10000)

    // RoPE the single q row at rank = last; zero g_Q behind the read
    if (tid < DD) {
        float freq = __expf(-LN_THETA * (float)(2 * (tid >> 1)) * (1.0f / 128.0f));
        float qv = g_Q[b][tid] + bq[tid];
        g_Q[b][tid] = 0.0f;
        float a = (float)last * freq;
        float cq = __cosf(a), sq = __sinf(a);
        float qp = __shfl_xor_sync(0xffffffffu, qv, 1);
        qs[tid] = ((tid & 1) == 0) ? (qv * cq - qp * sq) : (qp * sq + qv * cq);
    }
    __syncthreads();

    // logits from smem: warp w handles n = w, w+8, ...
    float fr[4];
#pragma unroll
    for (int s4 = 0; s4 < 4; s4++) {
        int dd = lane + s4 * 32;
        fr[s4] = __expf(-LN_THETA * (float)(2 * (dd >> 1)) * (1.0f / 128.0f));
    }
    for (int n = warp; n < cnt; n += 8) {
        float dot = 0.0f;
        float nf = (float)n;
#pragma unroll
        for (int s4 = 0; s4 < 4; s4++) {
            int dd = lane + s4 * 32;
            float kv = buf[n * DD + dd] + bk[dd];
            float a = nf * fr[s4];
            float cn = __cosf(a), sn = __sinf(a);
            float kp = __shfl_xor_sync(0xffffffffu, kv, 1);
            float kr = ((dd & 1) == 0) ? (kv * cn - kp * sn) : (kp * sn + kv * cn);
            dot += qs[dd] * kr;
        }
#pragma unroll
        for (int off = 16; off; off >>= 1)
            dot += __shfl_xor_sync(0xffffffffu, dot, off);
        if (lane == 0) lg[n] = dot * 0.08838834764831845f;  // 1/sqrt(128)
    }
    __syncthreads();

    // warp-parallel softmax + reward; then cross-batch join + loss
    if (warp == 0) {
        const float NEG = -3.0e38f;
        int n0 = lane, n1 = lane + 32;
        bool v0ok = (n0 < cnt), v1ok = (n1 < cnt);
        float l0 = v0ok ? lg[n0] : NEG;
        float l1 = v1ok ? lg[n1] : NEG;
        float mx = fmaxf(l0, l1);
#pragma unroll
        for (int off = 16; off; off >>= 1)
            mx = fmaxf(mx, __shfl_xor_sync(0xffffffffu, mx, off));

        float br0 = br[0];
        float e0 = v0ok ? __expf(l0 - mx) : 0.0f;
        float e1 = v1ok ? __expf(l1 - mx) : 0.0f;
        float vn0 = v0ok ? (sv[n0] + br0) : 0.0f;
        float vp0 = (v0ok && n0 > 0) ? (sv[n0 - 1] + br0) : 0.0f;
        float vn1 = v1ok ? (sv[n1] + br0) : 0.0f;
        float vp1 = v1ok ? (sv[n1 - 1] + br0) : 0.0f;
        float sum = e0 + e1;
        float rew = e0 * (vn0 - vp0) + e1 * (vn1 - vp1);
#pragma unroll
        for (int off = 16; off; off >>= 1) {
            sum += __shfl_xor_sync(0xffffffffu, sum, off);
            rew += __shfl_xor_sync(0xffffffffu, rew, off);
        }
        if (lane == 0) {
            g_rew[b] = rew / sum;
            __threadfence();
            int old2 = atomicAdd(&g_done, 1);
            if (old2 == BB - 1) {        // last batch: pairwise loss + output
                __threadfence();
                float r[BB];
#pragma unroll
                for (int k = 0; k < BB; k++) r[k] = g_rew[k];
                float loss = 0.0f;
#pragma unroll
                for (int k = 0; k < 4; k++) {
                    float x = r[k] - r[k + 4];
                    loss += (x >= 0.0f) ? log1pf(expf(-x))
                                        : (-x + log1pf(expf(x)));
                }
                loss *= 0.25f;
                if (out_size >= 9) {
                    out[0] = loss;
                    for (int k = 0; k < 8; k++) out[1 + k] = r[k];
                } else if (out_size == 8) {
                    for (int k = 0; k < 8; k++) out[k] = r[k];
                } else {
                    out[0] = loss;
                }
                g_done = 0;              // reset for next replay
            }
        }
    }
}

// ---------------------------------------------------------------------------
extern "C" void kernel_launch(void* const* d_in, const int* in_sizes, int n_in,
                              void* d_out, int out_size) {
    const float* hid  = (const float*)d_in[0];
    const int*   mask = (const int*)  d_in[1];
    const float* Wq   = (const float*)d_in[2];
    const float* bq   = (const float*)d_in[3];
    const float* Wk   = (const float*)d_in[4];
    const float* bk   = (const float*)d_in[5];
    const float* Wr   = (const float*)d_in[6];
    const float* br   = (const float*)d_in[7];
    float* out = (float*)d_out;

    k_fused<<<dim3(NT, BB), TPB>>>(hid, mask, Wq, bq, Wk, bk, Wr, br,
                                   out, out_size);
}

// round 10
// speedup vs baseline: 1.1920x; 1.1920x over previous
#include <cuda_runtime.h>
#include <math.h>

#define BB 8
#define SS 4096
#define HH 4096
#define DD 128
#define NMAX 64
#define NT 64
#define HT 64            /* HH / NT */
#define TPB 128

// -------- persistent scratch: zero at load; attn tail re-zeros each replay --
__device__ float g_K[BB][NMAX][DD];   // 256 KB
__device__ float g_Q[BB][DD];
__device__ float g_V[BB][NMAX];
__device__ float g_rew[BB];
__device__ int   g_arrive[BB];        // per-batch arrival counters
__device__ int   g_done;              // cross-batch arrival counter

__device__ __forceinline__ void red_f32(float* p, float v) {
    asm volatile("red.global.add.f32 [%0], %1;" :: "l"(p), "f"(v) : "memory");
}
__device__ __forceinline__ void red_v2(float* p, float x, float y) {
    asm volatile("red.global.add.v2.f32 [%0], {%1,%2};"
                 :: "l"(p), "f"(x), "f"(y) : "memory");
}

// ---------------------------------------------------------------------------
// ONE fused kernel. grid=(NT, BB), 128 threads (thread = output dim d).
// Phase 1: h-sliced projections; K/Q flushed as PAIRED red.v2 (halved L2
//          atomic ops vs scalar — lanes d and d^1 swap results via shfl).
// Phase 2 (last block per batch): attention + reward + accumulator re-zero.
// Phase 3 (last batch): pairwise loss + output.
// ---------------------------------------------------------------------------
__global__ void __launch_bounds__(TPB)
k_fused(const float* __restrict__ hid,
        const int*   __restrict__ mask,
        const float* __restrict__ Wq,
        const float* __restrict__ bq,
        const float* __restrict__ Wk,
        const float* __restrict__ bk,
        const float* __restrict__ Wr,
        const float* __restrict__ br,
        float* __restrict__ out, int out_size) {
    const int b    = blockIdx.y;
    const int tile = blockIdx.x;
    const int h0   = tile * HT;
    const int tid  = threadIdx.x;     // == d
    const int lane = tid & 31, warp = tid >> 5;

    __shared__ __align__(16) float buf[NMAX * DD];  // 32KB: proj 16KB, attn all
    __shared__ float swr[HT];
    __shared__ float qs[DD];
    __shared__ float lg[NMAX];
    __shared__ float sv[NMAX];
    __shared__ int   s_pos[NMAX];
    __shared__ int   s_wsum[4];
    __shared__ int   s_cnt;
    __shared__ int   s_last;

    // ---- issue Wk register preload FIRST (overlaps the scan below) ----
    unsigned long long wk2[HT / 2];
#pragma unroll
    for (int j = 0; j < HT / 2; j++) {
        float w0 = Wk[(size_t)(h0 + 2 * j) * DD + tid];
        float w1 = Wk[(size_t)(h0 + 2 * j + 1) * DD + tid];
        asm("mov.b64 %0,{%1,%2};" : "=l"(wk2[j]) : "f"(w0), "f"(w1));
    }
    if (tid < HT) swr[tid] = Wr[h0 + tid];

    // ---- inline mask scan: SINGLE pass, 128 threads x 32 elements ----
    {
        const int base = tid * 32;
        const int4* m4 = (const int4*)(mask + b * SS + base);
        int v[32];
#pragma unroll
        for (int q = 0; q < 8; q++) {
            int4 t4 = m4[q];
            v[4*q] = t4.x; v[4*q+1] = t4.y; v[4*q+2] = t4.z; v[4*q+3] = t4.w;
        }
        int c = 0;
#pragma unroll
        for (int j = 0; j < 32; j++) c += (v[j] > 0);
        int x = c;
#pragma unroll
        for (int off = 1; off < 32; off <<= 1) {
            int y = __shfl_up_sync(0xffffffffu, x, off);
            if (lane >= off) x += y;
        }
        if (lane == 31) s_wsum[warp] = x;
        __syncthreads();
        int pre = 0;
#pragma unroll
        for (int w = 0; w < 4; w++) pre += (w < warp) ? s_wsum[w] : 0;
        int r = pre + x - c;
#pragma unroll
        for (int j = 0; j < 32; j++) {
            if (v[j] > 0) { if (r < NMAX) s_pos[r] = base + j; r++; }
        }
        if (tid == 0) {
            int tot = s_wsum[0] + s_wsum[1] + s_wsum[2] + s_wsum[3];
            s_cnt = (tot < NMAX) ? tot : NMAX;
        }
        __syncthreads();
    }
    const int cnt  = s_cnt;
    const int last = cnt - 1;

    // ---- preload ALL sentence-row slices into smem (one MLP burst) ----
    {
        int tot4 = cnt * (HT / 4);
        float4* b4 = (float4*)buf;
        for (int i = tid; i < tot4; i += TPB) {
            int row = i >> 4;            // HT/4 = 16
            int c4  = i & 15;
            b4[i] = *(const float4*)(hid +
                ((size_t)b * SS + s_pos[row]) * HH + h0 + c4 * 4);
        }
    }
    __syncthreads();

    // ---- mainloop: 2 rows/iter, 4 FFMA2 chains, PAIRED v2 RED flush ----
    int i = 0;
    for (; i + 2 <= cnt; i += 2) {
        const ulonglong2* r0 = (const ulonglong2*)&buf[i * HT];
        const ulonglong2* r1 = (const ulonglong2*)&buf[(i + 1) * HT];
        unsigned long long a00 = 0ull, a01 = 0ull, a10 = 0ull, a11 = 0ull;
#pragma unroll
        for (int j = 0; j < HT / 4; j++) {
            ulonglong2 x0 = r0[j], x1 = r1[j];
            asm("fma.rn.f32x2 %0,%1,%2,%0;" : "+l"(a00) : "l"(x0.x), "l"(wk2[2*j]));
            asm("fma.rn.f32x2 %0,%1,%2,%0;" : "+l"(a10) : "l"(x1.x), "l"(wk2[2*j]));
            asm("fma.rn.f32x2 %0,%1,%2,%0;" : "+l"(a01) : "l"(x0.y), "l"(wk2[2*j+1]));
            asm("fma.rn.f32x2 %0,%1,%2,%0;" : "+l"(a11) : "l"(x1.y), "l"(wk2[2*j+1]));
        }
        float l0,h0f,l1,h1f,l2,h2f,l3,h3f;
        asm("mov.b64 {%0,%1},%2;" : "=f"(l0), "=f"(h0f) : "l"(a00));
        asm("mov.b64 {%0,%1},%2;" : "=f"(l1), "=f"(h1f) : "l"(a01));
        asm("mov.b64 {%0,%1},%2;" : "=f"(l2), "=f"(h2f) : "l"(a10));
        asm("mov.b64 {%0,%1},%2;" : "=f"(l3), "=f"(h3f) : "l"(a11));
        float k0 = (l0 + h0f) + (l1 + h1f);     // row i   @ d=tid
        float k1 = (l2 + h2f) + (l3 + h3f);     // row i+1 @ d=tid
        float p0 = __shfl_xor_sync(0xffffffffu, k0, 1);
        float p1 = __shfl_xor_sync(0xffffffffu, k1, 1);
        if ((tid & 1) == 0) red_v2(&g_K[b][i][tid], k0, p0);
        else                red_v2(&g_K[b][i + 1][tid - 1], p1, k1);

        if (tid < HT) {   // V partials for both rows (warps 0,1)
            float vp0 = buf[i * HT + tid] * swr[tid];
            float vp1 = buf[(i + 1) * HT + tid] * swr[tid];
#pragma unroll
            for (int off = 16; off; off >>= 1) {
                vp0 += __shfl_down_sync(0xffffffffu, vp0, off);
                vp1 += __shfl_down_sync(0xffffffffu, vp1, off);
            }
            if (lane == 0) {
                red_f32(&g_V[b][i], vp0);
                red_f32(&g_V[b][i + 1], vp1);
            }
        }
    }
    if (i < cnt) {       // odd tail row
        const ulonglong2* r0 = (const ulonglong2*)&buf[i * HT];
        unsigned long long a00 = 0ull, a01 = 0ull;
#pragma unroll
        for (int j = 0; j < HT / 4; j++) {
            ulonglong2 x0 = r0[j];
            asm("fma.rn.f32x2 %0,%1,%2,%0;" : "+l"(a00) : "l"(x0.x), "l"(wk2[2*j]));
            asm("fma.rn.f32x2 %0,%1,%2,%0;" : "+l"(a01) : "l"(x0.y), "l"(wk2[2*j+1]));
        }
        float l0,h0f,l1,h1f;
        asm("mov.b64 {%0,%1},%2;" : "=f"(l0), "=f"(h0f) : "l"(a00));
        asm("mov.b64 {%0,%1},%2;" : "=f"(l1), "=f"(h1f) : "l"(a01));
        float k0 = (l0 + h0f) + (l1 + h1f);
        float p0 = __shfl_xor_sync(0xffffffffu, k0, 1);
        if ((tid & 1) == 0) red_v2(&g_K[b][i][tid], k0, p0);
        if (tid < HT) {
            float vp0 = buf[i * HT + tid] * swr[tid];
#pragma unroll
            for (int off = 16; off; off >>= 1)
                vp0 += __shfl_down_sync(0xffffffffu, vp0, off);
            if (lane == 0) red_f32(&g_V[b][i], vp0);
        }
    }

    // ---- Q: h-slice of the last sentence row; paired v2 RED ----
    {
        const float* srow = &buf[last * HT];
        float aq0 = 0.0f, aq1 = 0.0f;
#pragma unroll
        for (int j = 0; j < HT; j += 2) {
            aq0 += srow[j]     * Wq[(size_t)(h0 + j) * DD + tid];
            aq1 += srow[j + 1] * Wq[(size_t)(h0 + j + 1) * DD + tid];
        }
        float aq = aq0 + aq1;
        float pq = __shfl_xor_sync(0xffffffffu, aq, 1);
        if ((tid & 1) == 0) red_v2(&g_Q[b][tid], aq, pq);
    }

    // ---- arrival: last block of this batch proceeds to attention ----
    __threadfence();
    __syncthreads();
    if (tid == 0) {
        int old = atomicAdd(&g_arrive[b], 1);
        s_last = (old == NT - 1);
        if (s_last) g_arrive[b] = 0;     // reset for next replay
    }
    __syncthreads();
    if (!s_last) return;
    __threadfence();                     // acquire: make all REDs visible

    // =================== attention tail (1 block per batch) ================
    // burst g_K[b] into smem; zero it behind the read
    {
        float4* b4 = (float4*)buf;
        float4 z = make_float4(0.f, 0.f, 0.f, 0.f);
        int tot = cnt * (DD / 4);
        for (int ii = tid; ii < tot; ii += TPB) {
            int row = ii >> 5, c4 = ii & 31;
            float4 v = *(const float4*)&g_K[b][row][c4 * 4];
            b4[ii] = v;
            *(float4*)&g_K[b][row][c4 * 4] = z;
        }
    }
    if (tid < NMAX) { sv[tid] = g_V[b][tid]; g_V[b][tid] = 0.0f; }

    const float LN_THETA = 9.210340371976184f;   // ln(10000)

    // RoPE the single q row at rank = last; zero g_Q behind the read
    {
        float freq = __expf(-LN_THETA * (float)(2 * (tid >> 1)) * (1.0f / 128.0f));
        float qv = g_Q[b][tid] + bq[tid];
        g_Q[b][tid] = 0.0f;
        float a = (float)last * freq;
        float cq = __cosf(a), sq = __sinf(a);
        float qp = __shfl_xor_sync(0xffffffffu, qv, 1);
        qs[tid] = ((tid & 1) == 0) ? (qv * cq - qp * sq) : (qp * sq + qv * cq);
    }
    __syncthreads();

    // logits from smem: warp w handles n = w, w+4, ...
    float fr[4];
#pragma unroll
    for (int s4 = 0; s4 < 4; s4++) {
        int dd = lane + s4 * 32;
        fr[s4] = __expf(-LN_THETA * (float)(2 * (dd >> 1)) * (1.0f / 128.0f));
    }
    for (int n = warp; n < cnt; n += 4) {
        float dot = 0.0f;
        float nf = (float)n;
#pragma unroll
        for (int s4 = 0; s4 < 4; s4++) {
            int dd = lane + s4 * 32;
            float kv = buf[n * DD + dd] + bk[dd];
            float a = nf * fr[s4];
            float cn = __cosf(a), sn = __sinf(a);
            float kp = __shfl_xor_sync(0xffffffffu, kv, 1);
            float kr = ((dd & 1) == 0) ? (kv * cn - kp * sn) : (kp * sn + kv * cn);
            dot += qs[dd] * kr;
        }
#pragma unroll
        for (int off = 16; off; off >>= 1)
            dot += __shfl_xor_sync(0xffffffffu, dot, off);
        if (lane == 0) lg[n] = dot * 0.08838834764831845f;  // 1/sqrt(128)
    }
    __syncthreads();

    // warp-parallel softmax + reward; then cross-batch join + loss
    if (warp == 0) {
        const float NEG = -3.0e38f;
        int n0 = lane, n1 = lane + 32;
        bool v0ok = (n0 < cnt), v1ok = (n1 < cnt);
        float l0 = v0ok ? lg[n0] : NEG;
        float l1 = v1ok ? lg[n1] : NEG;
        float mx = fmaxf(l0, l1);
#pragma unroll
        for (int off = 16; off; off >>= 1)
            mx = fmaxf(mx, __shfl_xor_sync(0xffffffffu, mx, off));

        float br0 = br[0];
        float e0 = v0ok ? __expf(l0 - mx) : 0.0f;
        float e1 = v1ok ? __expf(l1 - mx) : 0.0f;
        float vn0 = v0ok ? (sv[n0] + br0) : 0.0f;
        float vp0 = (v0ok && n0 > 0) ? (sv[n0 - 1] + br0) : 0.0f;
        float vn1 = v1ok ? (sv[n1] + br0) : 0.0f;
        float vp1 = v1ok ? (sv[n1 - 1] + br0) : 0.0f;
        float sum = e0 + e1;
        float rew = e0 * (vn0 - vp0) + e1 * (vn1 - vp1);
#pragma unroll
        for (int off = 16; off; off >>= 1) {
            sum += __shfl_xor_sync(0xffffffffu, sum, off);
            rew += __shfl_xor_sync(0xffffffffu, rew, off);
        }
        if (lane == 0) {
            g_rew[b] = rew / sum;
            __threadfence();
            int old2 = atomicAdd(&g_done, 1);
            if (old2 == BB - 1) {        // last batch: pairwise loss + output
                __threadfence();
                float r[BB];
#pragma unroll
                for (int k = 0; k < BB; k++) r[k] = g_rew[k];
                float loss = 0.0f;
#pragma unroll
                for (int k = 0; k < 4; k++) {
                    float x = r[k] - r[k + 4];
                    loss += (x >= 0.0f) ? log1pf(expf(-x))
                                        : (-x + log1pf(expf(x)));
                }
                loss *= 0.25f;
                if (out_size >= 9) {
                    out[0] = loss;
                    for (int k = 0; k < 8; k++) out[1 + k] = r[k];
                } else if (out_size == 8) {
                    for (int k = 0; k < 8; k++) out[k] = r[k];
                } else {
                    out[0] = loss;
                }
                g_done = 0;              // reset for next replay
            }
        }
    }
}

// ---------------------------------------------------------------------------
extern "C" void kernel_launch(void* const* d_in, const int* in_sizes, int n_in,
                              void* d_out, int out_size) {
    const float* hid  = (const float*)d_in[0];
    const int*   mask = (const int*)  d_in[1];
    const float* Wq   = (const float*)d_in[2];
    const float* bq   = (const float*)d_in[3];
    const float* Wk   = (const float*)d_in[4];
    const float* bk   = (const float*)d_in[5];
    const float* Wr   = (const float*)d_in[6];
    const float* br   = (const float*)d_in[7];
    float* out = (float*)d_out;

    k_fused<<<dim3(NT, BB), TPB>>>(hid, mask, Wq, bq, Wk, bk, Wr, br,
                                   out, out_size);
}